// round 16
// baseline (speedup 1.0000x reference)
#include <cuda_runtime.h>
#include <cstdint>

#define BB      8
#define CTOT    256
#define HH      96
#define WW      128
#define CK      16                 // channels per chunk (2 k8 steps)
#define NCH     (CTOT/CK)          // 16
#define THREADS 288                // 9 warps, one dy each
#define CHS     (HH*WW)

#define SB_K       224                         // bytes per (dy,k) row (48 floats)
#define SB_DY      (CK*SB_K)                   // 3584
#define BUFB       (9*SB_DY)                   // 32256 per buffer
#define SMEM_TOTAL (2*BUFB)                    // 64512 -> 3 blocks/SM

__device__ __forceinline__ void cpa16(uint32_t dst, const float* src) {
    asm volatile("cp.async.cg.shared.global [%0], [%1], 16;" :: "r"(dst), "l"(src));
}
__device__ __forceinline__ void sts_zero16(uint32_t addr) {
    asm volatile("st.shared.v4.b32 [%0], {%1,%1,%1,%1};" :: "r"(addr), "r"(0) : "memory");
}
__device__ __forceinline__ float lds32(uint32_t a) {
    float v;
    asm volatile("ld.shared.f32 %0, [%1];" : "=f"(v) : "r"(a));
    return v;
}
__device__ __forceinline__ uint32_t tf32c(float x) {
    uint32_t r;
    asm("cvt.rna.tf32.f32 %0, %1;" : "=r"(r) : "f"(x));
    return r;
}
__device__ __forceinline__ void mma8(float* d, const uint32_t* a, const uint32_t* b) {
    asm volatile(
        "mma.sync.aligned.m16n8k8.row.col.f32.tf32.tf32.f32 "
        "{%0,%1,%2,%3}, {%4,%5,%6,%7}, {%8,%9}, {%0,%1,%2,%3};"
        : "+f"(d[0]), "+f"(d[1]), "+f"(d[2]), "+f"(d[3])
        : "r"(a[0]), "r"(a[1]), "r"(a[2]), "r"(a[3]), "r"(b[0]), "r"(b[1]));
}

__global__ void __launch_bounds__(THREADS, 3)
corr_kernel(const float* __restrict__ in1, const float* __restrict__ in2,
            float* __restrict__ out)
{
    extern __shared__ char smem[];
    const uint32_t smem32 = (uint32_t)__cvta_generic_to_shared(smem);

    const int tid  = threadIdx.x;
    const int warp = tid >> 5;         // dy 0..8
    const int lane = tid & 31;
    const int gid  = lane >> 2;        // mma groupID (0..7)
    const int tig  = lane & 3;         // thread-in-group (0..3)

    const int bx  = blockIdx.x;
    const int b   = bx / 384;
    const int rem = bx - b * 384;
    const int h   = rem >> 2;
    const int X0  = (rem & 3) * 32;

    const int hB = h + warp - 4;
    const bool rowOK = (hB >= 0) && (hB < HH);   // warp-uniform

    // Division-free loader mapping: lane -> (k-row, half of the 12 chunks)
    const int lk    = lane >> 1;        // k 0..15
    const int lhalf = lane & 1;         // chunks [half*6, half*6+6)
    bool cp[6];
#pragma unroll
    for (int it = 0; it < 6; it++) {
        int col = X0 - 8 + 4 * (lhalf * 6 + it);
        cp[it] = (col >= 0) && (col <= WW - 4);
    }

    const uint32_t wB0 = smem32 + (uint32_t)(warp * SB_DY);
    const uint32_t wB1 = wB0 + BUFB;
    const uint32_t dst0 = (uint32_t)(lk * SB_K + lhalf * 96);

    // Pre-zero invalid (col-OOB) chunks in this lane's k-row, both buffers.
    if (rowOK) {
#pragma unroll
        for (int it = 0; it < 6; it++) {
            if (!cp[it]) {
                sts_zero16(wB0 + dst0 + it * 16);
                sts_zero16(wB1 + dst0 + it * 16);
            }
        }
    }
    __syncwarp();

    float acc[6][4];
#pragma unroll
    for (int e = 0; e < 6; e++)
#pragma unroll
        for (int j = 0; j < 4; j++) acc[e][j] = 0.f;

    if (rowOK) {
        // B source: this warp's row, this lane's k-channel + chunk-half
        const float* sBsrc = in2 + ((size_t)(b * CTOT + lk) * HH + hB) * WW
                           + X0 - 8 + lhalf * 24;
        // A source: direct LDG (L1-shared across the 9 warps)
        const float* pAt = in1 + (size_t)(b * CTOT + tig) * CHS + h * WW + X0 + gid;

        // Prologue: chunk 0 -> buf0
        {
#pragma unroll
            for (int it = 0; it < 6; it++)
                if (cp[it]) cpa16(wB0 + dst0 + it * 16, sBsrc + it * 4);
            asm volatile("cp.async.commit_group;" ::: "memory");
            sBsrc += (size_t)CK * CHS;
        }

        for (int kc = 0; kc < NCH; kc++) {
            if (kc + 1 < NCH) {
                const uint32_t wbn = (kc & 1) ? wB0 : wB1;
#pragma unroll
                for (int it = 0; it < 6; it++)
                    if (cp[it]) cpa16(wbn + dst0 + it * 16, sBsrc + it * 4);
                asm volatile("cp.async.commit_group;" ::: "memory");
                sBsrc += (size_t)CK * CHS;
                asm volatile("cp.async.wait_group 1;" ::: "memory");
            } else {
                asm volatile("cp.async.wait_group 0;" ::: "memory");
            }
            __syncwarp();

            const uint32_t wBc = (kc & 1) ? wB1 : wB0;
#pragma unroll
            for (int s = 0; s < 2; s++) {
                uint32_t a[2][4];
#pragma unroll
                for (int T = 0; T < 2; T++) {
                    const float* ap = pAt + (size_t)(s * 8) * CHS + 16 * T;
                    a[T][0] = tf32c(__ldg(ap));
                    a[T][1] = tf32c(__ldg(ap + 8));
                    a[T][2] = tf32c(__ldg(ap + 4 * CHS));
                    a[T][3] = tf32c(__ldg(ap + 4 * CHS + 8));
                }
                uint32_t bf[5][2];
                const uint32_t bk = wBc + (uint32_t)((s * 8 + tig) * SB_K + (4 + gid) * 4);
#pragma unroll
                for (int nb = 0; nb < 5; nb++) {
                    bf[nb][0] = tf32c(lds32(bk + nb * 32));
                    bf[nb][1] = tf32c(lds32(bk + nb * 32 + 4 * SB_K));
                }
                mma8(acc[0], a[0], bf[0]);
                mma8(acc[1], a[0], bf[1]);
                mma8(acc[2], a[0], bf[2]);
                mma8(acc[3], a[1], bf[2]);
                mma8(acc[4], a[1], bf[3]);
                mma8(acc[5], a[1], bf[4]);
            }
            pAt += (size_t)CK * CHS;
        }
    }

    // Epilogue: acc entry (row,n) -> x = X0+16T+row, d = 8*nb + n - 16T - row
    const float inv = 1.0f / 256.0f;
#pragma unroll
    for (int e = 0; e < 6; e++) {
        const int T  = (e < 3) ? 0 : 1;
        const int nb = (e < 3) ? e : e - 1;
#pragma unroll
        for (int j = 0; j < 4; j++) {
            int row = gid + ((j >> 1) << 3);
            int n   = 2 * tig + (j & 1);
            int d   = 8 * nb + n - 16 * T - row;
            if (d >= 0 && d <= 8) {
                int x = X0 + 16 * T + row;
                out[((size_t)((b * 81 + warp * 9 + d)) * HH + h) * WW + x] = acc[e][j] * inv;
            }
        }
    }
}

extern "C" void kernel_launch(void* const* d_in, const int* in_sizes, int n_in,
                              void* d_out, int out_size)
{
    const float* in1 = (const float*)d_in[0];
    const float* in2 = (const float*)d_in[1];
    float* out = (float*)d_out;

    cudaFuncSetAttribute(corr_kernel, cudaFuncAttributeMaxDynamicSharedMemorySize, SMEM_TOTAL);
    corr_kernel<<<BB * HH * 4, THREADS, SMEM_TOTAL>>>(in1, in2, out);
}

// round 17
// speedup vs baseline: 1.0036x; 1.0036x over previous
#include <cuda_runtime.h>
#include <cstdint>

#define BB      8
#define CTOT    256
#define HH      96
#define WW      128
#define CK      16                 // channels per chunk (2 k8 steps)
#define NCH     (CTOT/CK)          // 16
#define THREADS 288                // 9 warps, one dy each
#define CHS     (HH*WW)

// smem strides (bytes), padded for conflict-free fragment loads
#define SA_K       160                         // A: per-channel row (32 floats used)
#define SA_BYTES   (CK*SA_K)                   // 2560
#define SB_K       224                         // B: per-channel row (48 floats used)
#define SB_DY      (CK*SB_K)                   // 3584
#define SB_BYTES   (9*SB_DY)                   // 32256
#define BUF_BYTES  (SA_BYTES+SB_BYTES)         // 34816
#define SMEM_TOTAL (2*BUF_BYTES)               // 69632 -> 3 blocks/SM

#define NBCH       1728                        // B 16B-chunks per buffer (9*16*12)

__device__ __forceinline__ void cpa16(uint32_t dst, const float* src) {
    asm volatile("cp.async.cg.shared.global [%0], [%1], 16;" :: "r"(dst), "l"(src));
}
__device__ __forceinline__ void sts_zero16(uint32_t addr) {
    asm volatile("st.shared.v4.b32 [%0], {%1,%1,%1,%1};" :: "r"(addr), "r"(0) : "memory");
}
__device__ __forceinline__ float lds32(uint32_t a) {
    float v;
    asm volatile("ld.shared.f32 %0, [%1];" : "=f"(v) : "r"(a));
    return v;
}
__device__ __forceinline__ uint32_t tf32c(float x) {
    uint32_t r;
    asm("cvt.rna.tf32.f32 %0, %1;" : "=r"(r) : "f"(x));
    return r;
}
__device__ __forceinline__ void mma8(float* d, const uint32_t* a, const uint32_t* b) {
    asm volatile(
        "mma.sync.aligned.m16n8k8.row.col.f32.tf32.tf32.f32 "
        "{%0,%1,%2,%3}, {%4,%5,%6,%7}, {%8,%9}, {%0,%1,%2,%3};"
        : "+f"(d[0]), "+f"(d[1]), "+f"(d[2]), "+f"(d[3])
        : "r"(a[0]), "r"(a[1]), "r"(a[2]), "r"(a[3]), "r"(b[0]), "r"(b[1]));
}

__global__ void __launch_bounds__(THREADS, 3)
corr_kernel(const float* __restrict__ in1, const float* __restrict__ in2,
            float* __restrict__ out)
{
    extern __shared__ char smem[];
    const uint32_t smem32 = (uint32_t)__cvta_generic_to_shared(smem);

    const int tid  = threadIdx.x;
    const int warp = tid >> 5;         // dy 0..8
    const int lane = tid & 31;
    const int gid  = lane >> 2;        // mma groupID (0..7)
    const int tig  = lane & 3;         // thread-in-group (0..3)

    const int bx  = blockIdx.x;
    const int b   = bx / 384;
    const int rem = bx - b * 384;
    const int h   = rem >> 2;
    const int X0  = (rem & 3) * 32;

    // ---- One-time pre-zero of OOB B chunks in BOTH buffers (div OK here) ----
    for (int idx = tid; idx < NBCH; idx += THREADS) {
        int dyk = idx / 12, i = idx - dyk * 12;
        int dy = dyk >> 4, k = dyk & 15;
        int hBz = h + dy - 4;
        int col = X0 - 8 + i * 4;
        if (!(hBz >= 0 && hBz < HH && col >= 0 && col <= WW - 4)) {
            uint32_t off = SA_BYTES + dy * SB_DY + k * SB_K + i * 16;
            sts_zero16(smem32 + off);
            sts_zero16(smem32 + BUF_BYTES + off);
        }
    }

    // ---- Precomputed division-free loader state ----
    // B: warp w handles dy=w; lane -> (k = lane>>1, half = lane&1, 6 chunks)
    const int hB = h + warp - 4;
    const bool rowOK = (hB >= 0) && (hB < HH);
    const int lk    = lane >> 1;
    const int lhalf = lane & 1;
    uint32_t bMask = 0;
#pragma unroll
    for (int it = 0; it < 6; it++) {
        int col = X0 - 8 + 4 * (lhalf * 6 + it);
        if (col >= 0 && col <= WW - 4) bMask |= (1u << it);
    }
    const uint32_t dstB = (uint32_t)(SA_BYTES + warp * SB_DY + lk * SB_K + lhalf * 96);
    const float* pBbase = in2 + ((size_t)(b * CTOT + lk) * HH + (rowOK ? hB : 0)) * WW
                        + X0 - 8 + lhalf * 24;
    // A: threads 0..127 -> (k = tid>>3, i = tid&7)
    const bool aLoad = (tid < 128);
    const uint32_t dstA = (uint32_t)((tid >> 3) * SA_K + (tid & 7) * 16);
    const float* pAbase = in1 + ((size_t)(b * CTOT + (tid >> 3)) * HH + h) * WW
                        + X0 + (tid & 7) * 4;

    __syncthreads();   // pre-zero visible before any cp.async

    float acc[6][4];
#pragma unroll
    for (int e = 0; e < 6; e++)
#pragma unroll
        for (int j = 0; j < 4; j++) acc[e][j] = 0.f;

    // ---- Prologue: chunk 0 -> buffer 0 ----
    size_t kcOff = 0;
    {
        if (aLoad) cpa16(smem32 + dstA, pAbase);
        if (rowOK) {
#pragma unroll
            for (int it = 0; it < 6; it++)
                if (bMask & (1u << it)) cpa16(smem32 + dstB + it * 16, pBbase + it * 4);
        }
        asm volatile("cp.async.commit_group;" ::: "memory");
        kcOff += (size_t)CK * CHS;
    }

    for (int kc = 0; kc < NCH; kc++) {
        if (kc + 1 < NCH) {
            const uint32_t nb = smem32 + (uint32_t)(((kc + 1) & 1) * BUF_BYTES);
            if (aLoad) cpa16(nb + dstA, pAbase + kcOff);
            if (rowOK) {
                const float* s = pBbase + kcOff;
#pragma unroll
                for (int it = 0; it < 6; it++)
                    if (bMask & (1u << it)) cpa16(nb + dstB + it * 16, s + it * 4);
            }
            asm volatile("cp.async.commit_group;" ::: "memory");
            kcOff += (size_t)CK * CHS;
            asm volatile("cp.async.wait_group 1;" ::: "memory");
        } else {
            asm volatile("cp.async.wait_group 0;" ::: "memory");
        }
        __syncthreads();

        const uint32_t buf = smem32 + (uint32_t)((kc & 1) * BUF_BYTES);
        const uint32_t sB  = buf + SA_BYTES + warp * SB_DY;
#pragma unroll
        for (int s = 0; s < 2; s++) {
            // A fragments: two m16 tiles, row-major m16k8
            uint32_t a[2][4];
            const uint32_t ak = buf + (s * 8 + tig) * SA_K;
#pragma unroll
            for (int T = 0; T < 2; T++) {
                uint32_t base = ak + (uint32_t)((16 * T + gid) * 4);
                a[T][0] = tf32c(lds32(base));
                a[T][1] = tf32c(lds32(base + 32));
                a[T][2] = tf32c(lds32(base + 4 * SA_K));
                a[T][3] = tf32c(lds32(base + 4 * SA_K + 32));
            }
            // B fragments: 5 n-blocks (col-major k8n8), col' = 4 + 8*nb + gid
            uint32_t bf[5][2];
            const uint32_t bk = sB + (s * 8 + tig) * SB_K + (uint32_t)((4 + gid) * 4);
#pragma unroll
            for (int nbk = 0; nbk < 5; nbk++) {
                bf[nbk][0] = tf32c(lds32(bk + nbk * 32));
                bf[nbk][1] = tf32c(lds32(bk + nbk * 32 + 4 * SB_K));
            }
            mma8(acc[0], a[0], bf[0]);
            mma8(acc[1], a[0], bf[1]);
            mma8(acc[2], a[0], bf[2]);
            mma8(acc[3], a[1], bf[2]);
            mma8(acc[4], a[1], bf[3]);
            mma8(acc[5], a[1], bf[4]);
        }
        __syncthreads();
    }

    // Epilogue: acc entry (row,n) -> x = X0+16T+row, d = 8*nb + n - 16T - row
    const float inv = 1.0f / 256.0f;
#pragma unroll
    for (int e = 0; e < 6; e++) {
        const int T  = (e < 3) ? 0 : 1;
        const int nb = (e < 3) ? e : e - 1;
#pragma unroll
        for (int j = 0; j < 4; j++) {
            int row = gid + ((j >> 1) << 3);
            int n   = 2 * tig + (j & 1);
            int d   = 8 * nb + n - 16 * T - row;
            if (d >= 0 && d <= 8) {
                int x = X0 + 16 * T + row;
                out[((size_t)((b * 81 + warp * 9 + d)) * HH + h) * WW + x] = acc[e][j] * inv;
            }
        }
    }
}

extern "C" void kernel_launch(void* const* d_in, const int* in_sizes, int n_in,
                              void* d_out, int out_size)
{
    const float* in1 = (const float*)d_in[0];
    const float* in2 = (const float*)d_in[1];
    float* out = (float*)d_out;

    cudaFuncSetAttribute(corr_kernel, cudaFuncAttributeMaxDynamicSharedMemorySize, SMEM_TOTAL);
    corr_kernel<<<BB * HH * 4, THREADS, SMEM_TOTAL>>>(in1, in2, out);
}